// round 1
// baseline (speedup 1.0000x reference)
#include <cuda_runtime.h>
#include <math.h>
#include <stdint.h>

#define Bdim  4096
#define Fdim  4096
#define Vdim  1024
#define Edim  512
#define Hdim  1024
#define Ldim  30
#define LP1   (Ldim + 1)
#define BOUNDT 1023
#define G4H   (4 * Hdim)

// ---------------- scratch (static device globals; no allocation) ----------------
__device__ float g_Ts[(size_t)Vdim * G4H];      // emb_s @ Wih^T + bih + bhh   [V,4H]
__device__ float g_Tr[(size_t)Vdim * G4H];      // emb_r @ rWih^T + rbih + rbhh
__device__ float g_hA[(size_t)Bdim * Hdim];
__device__ float g_hB[(size_t)Bdim * Hdim];
__device__ float g_c [(size_t)Bdim * Hdim];
__device__ float g_scores[(size_t)Bdim * Vdim];
__device__ float g_r[(size_t)Bdim * Fdim];
__device__ float g_nwc[Vdim];
__device__ float g_vl[Bdim];
__device__ int   g_tok[Bdim];
__device__ int   g_sl[Bdim];
__device__ int   g_m[(size_t)Bdim * LP1];
__device__ int   g_wcnt[Vdim];
__device__ float g_loss_sum;
__device__ float g_acc_sum;

// ---------------- helpers ----------------
__device__ __forceinline__ float sigf(float x) {
    if (x >= 0.f) return 1.f / (1.f + expf(-x));
    float e = expf(x);
    return e / (1.f + e);
}

// ---------------- init ----------------
__global__ void init_kernel() {
    int idx = blockIdx.x * blockDim.x + threadIdx.x;
    if (idx < Bdim * Hdim) g_c[idx] = 0.f;
    if (idx < Bdim) {
        g_tok[idx] = BOUNDT;
        g_sl[idx]  = LP1;          // init_len = L+1
        g_vl[idx]  = 0.f;
        g_m[(size_t)idx * LP1] = BOUNDT;
    }
    if (idx < Vdim) g_wcnt[idx] = 0;
    if (idx == 0) { g_loss_sum = 0.f; g_acc_sum = 0.f; }
}

__global__ void zero_hc_kernel() {
    int idx = blockIdx.x * blockDim.x + threadIdx.x;
    if (idx < Bdim * Hdim) { g_hA[idx] = 0.f; g_c[idx] = 0.f; }
}

// normalized word counts: wc[BOUND]*=0.1; nwc = wc / sum(wc)
__global__ void nwc_kernel(const float* __restrict__ wc) {
    __shared__ float red[1024];
    int t = threadIdx.x;
    float v = wc[t];
    if (t == BOUNDT) v *= 0.1f;
    red[t] = v;
    __syncthreads();
    for (int s = 512; s > 0; s >>= 1) {
        if (t < s) red[t] += red[t + s];
        __syncthreads();
    }
    float denom = red[0];
    g_nwc[t] = (denom > 0.f) ? v / denom : v;
}

// ---------------- generic SGEMM: C[M,N] = A[M,K] @ B[N,K]^T + bias1 + bias2 ----------------
// Tiles 64x64x16, 256 threads, 4x4 per-thread microtile. M,N %64==0, K%16==0.
__global__ __launch_bounds__(256)
void sgemm_nt(const float* __restrict__ A, const float* __restrict__ Bm,
              const float* __restrict__ bias1, const float* __restrict__ bias2,
              float* __restrict__ C, int M, int N, int K) {
    __shared__ __align__(16) float As[16][64];
    __shared__ __align__(16) float Bs[16][64];
    int tid = threadIdx.x;
    int tx = tid & 15, ty = tid >> 4;
    int m0 = blockIdx.y * 64, n0 = blockIdx.x * 64;
    int lrow = tid >> 2, lcol = (tid & 3) * 4;

    float acc[4][4] = {};
    for (int k0 = 0; k0 < K; k0 += 16) {
        float4 av = *(const float4*)(A  + (size_t)(m0 + lrow) * K + k0 + lcol);
        float4 bv = *(const float4*)(Bm + (size_t)(n0 + lrow) * K + k0 + lcol);
        As[lcol + 0][lrow] = av.x; As[lcol + 1][lrow] = av.y;
        As[lcol + 2][lrow] = av.z; As[lcol + 3][lrow] = av.w;
        Bs[lcol + 0][lrow] = bv.x; Bs[lcol + 1][lrow] = bv.y;
        Bs[lcol + 2][lrow] = bv.z; Bs[lcol + 3][lrow] = bv.w;
        __syncthreads();
#pragma unroll
        for (int k = 0; k < 16; k++) {
            float4 a = *(const float4*)&As[k][ty << 2];
            float4 b = *(const float4*)&Bs[k][tx << 2];
            float ar[4] = {a.x, a.y, a.z, a.w};
            float br[4] = {b.x, b.y, b.z, b.w};
#pragma unroll
            for (int i = 0; i < 4; i++)
#pragma unroll
                for (int j = 0; j < 4; j++) acc[i][j] += ar[i] * br[j];
        }
        __syncthreads();
    }
    float bb[4];
#pragma unroll
    for (int j = 0; j < 4; j++) {
        int n = n0 + (tx << 2) + j;
        bb[j] = (bias1 ? bias1[n] : 0.f) + (bias2 ? bias2[n] : 0.f);
    }
#pragma unroll
    for (int i = 0; i < 4; i++) {
        float4 o = make_float4(acc[i][0] + bb[0], acc[i][1] + bb[1],
                               acc[i][2] + bb[2], acc[i][3] + bb[3]);
        *(float4*)(C + (size_t)(m0 + (ty << 2) + i) * N + n0 + (tx << 2)) = o;
    }
}

// ---------------- fused LSTM step ----------------
// For row-tile x hcol-tile, compute all 4 gate GEMM tiles (h_prev @ Whh^T),
// seeded with the gathered x-projection table row, then apply the LSTM cell.
__global__ __launch_bounds__(256, 2)
void lstm_step(const float* __restrict__ h_in, float* __restrict__ c_io,
               float* __restrict__ h_out,
               const float* __restrict__ Whh,  // [4H, H]
               const float* __restrict__ T,    // [V, 4H] (biases folded in)
               const int* __restrict__ tok, int tok_stride) {
    __shared__ __align__(16) float As[16][64];
    __shared__ __align__(16) float Bs[4][16][64];
    int tid = threadIdx.x;
    int tx = tid & 15, ty = tid >> 4;
    int m0 = blockIdx.y * 64;   // batch rows
    int n0 = blockIdx.x * 64;   // h columns
    int lrow = tid >> 2, lcol = (tid & 3) * 4;

    float acc[4][4][4];   // [gate][i][j]
    // seed with gathered table rows
#pragma unroll
    for (int i = 0; i < 4; i++) {
        int row = m0 + (ty << 2) + i;
        int t_r = tok[(size_t)row * tok_stride];
        const float* Trow = T + (size_t)t_r * G4H + n0 + (tx << 2);
#pragma unroll
        for (int g = 0; g < 4; g++) {
            float4 v = *(const float4*)(Trow + g * Hdim);
            acc[g][i][0] = v.x; acc[g][i][1] = v.y;
            acc[g][i][2] = v.z; acc[g][i][3] = v.w;
        }
    }

    for (int k0 = 0; k0 < Hdim; k0 += 16) {
        float4 av = *(const float4*)(h_in + (size_t)(m0 + lrow) * Hdim + k0 + lcol);
        As[lcol + 0][lrow] = av.x; As[lcol + 1][lrow] = av.y;
        As[lcol + 2][lrow] = av.z; As[lcol + 3][lrow] = av.w;
#pragma unroll
        for (int g = 0; g < 4; g++) {
            float4 bv = *(const float4*)(Whh + (size_t)(g * Hdim + n0 + lrow) * Hdim + k0 + lcol);
            Bs[g][lcol + 0][lrow] = bv.x; Bs[g][lcol + 1][lrow] = bv.y;
            Bs[g][lcol + 2][lrow] = bv.z; Bs[g][lcol + 3][lrow] = bv.w;
        }
        __syncthreads();
#pragma unroll
        for (int k = 0; k < 16; k++) {
            float4 a = *(const float4*)&As[k][ty << 2];
            float ar[4] = {a.x, a.y, a.z, a.w};
#pragma unroll
            for (int g = 0; g < 4; g++) {
                float4 b = *(const float4*)&Bs[g][k][tx << 2];
                float br[4] = {b.x, b.y, b.z, b.w};
#pragma unroll
                for (int i = 0; i < 4; i++)
#pragma unroll
                    for (int j = 0; j < 4; j++) acc[g][i][j] += ar[i] * br[j];
            }
        }
        __syncthreads();
    }

    // LSTM cell epilogue (gate order: i, f, g, o)
#pragma unroll
    for (int i = 0; i < 4; i++) {
        int row = m0 + (ty << 2) + i;
#pragma unroll
        for (int j = 0; j < 4; j++) {
            int n = n0 + (tx << 2) + j;
            size_t off = (size_t)row * Hdim + n;
            float ig = acc[0][i][j], fg = acc[1][i][j];
            float gg = acc[2][i][j], og = acc[3][i][j];
            float c_old = c_io[off];
            float cn = sigf(fg) * c_old + sigf(ig) * tanhf(gg);
            float hn = sigf(og) * tanhf(cn);
            c_io[off] = cn;
            h_out[off] = hn;
        }
    }
}

// ---------------- per-row argmax + CE over V=1024 scores (warp per row) ----------------
__global__ void score_reduce(const float* __restrict__ scores, int step) {
    int gwarp = (blockIdx.x * blockDim.x + threadIdx.x) >> 5;
    int lane = threadIdx.x & 31;
    if (gwarp >= Bdim) return;
    const float* srow = scores + (size_t)gwarp * Vdim;

    float lvals[32];
    float best = -INFINITY; int bidx = 0;
    float lmax = -INFINITY;
#pragma unroll
    for (int j = 0; j < 32; j++) {
        int idx = lane + j * 32;
        float s = srow[idx];
        float l = s - g_nwc[idx];
        lvals[j] = l;
        if (s > best) { best = s; bidx = idx; }   // strict >: first index wins ties
        lmax = fmaxf(lmax, l);
    }
#pragma unroll
    for (int off = 16; off; off >>= 1) {
        float ov = __shfl_down_sync(0xffffffffu, best, off);
        int   oi = __shfl_down_sync(0xffffffffu, bidx, off);
        if (ov > best || (ov == best && oi < bidx)) { best = ov; bidx = oi; }
        lmax = fmaxf(lmax, __shfl_down_sync(0xffffffffu, lmax, off));
    }
    bidx = __shfl_sync(0xffffffffu, bidx, 0);
    lmax = __shfl_sync(0xffffffffu, lmax, 0);

    float se = 0.f;
#pragma unroll
    for (int j = 0; j < 32; j++) se += expf(lvals[j] - lmax);
#pragma unroll
    for (int off = 16; off; off >>= 1) se += __shfl_down_sync(0xffffffffu, se, off);

    if (lane == 0) {
        float l_tok = srow[bidx] - g_nwc[bidx];
        float ce = logf(se) + lmax - l_tok;      // -log_softmax at new token
        g_m[(size_t)gwarp * LP1 + step + 1] = bidx;
        g_tok[gwarp] = bidx;
        if (bidx == BOUNDT && g_sl[gwarp] == LP1) g_sl[gwarp] = step + 2;
        g_vl[gwarp] += ce;
    }
}

// ---------------- pad m past seq length with bound token ----------------
__global__ void pad_kernel() {
    int idx = blockIdx.x * blockDim.x + threadIdx.x;
    if (idx >= Bdim * LP1) return;
    int b = idx / LP1, p = idx % LP1;
    if (p >= g_sl[b]) g_m[idx] = BOUNDT;
}

// ---------------- histogram of m into g_wcnt ----------------
__global__ void hist_kernel() {
    __shared__ int hs[Vdim];
    for (int i = threadIdx.x; i < Vdim; i += blockDim.x) hs[i] = 0;
    __syncthreads();
    int total = Bdim * LP1;
    for (int idx = blockIdx.x * blockDim.x + threadIdx.x; idx < total;
         idx += gridDim.x * blockDim.x)
        atomicAdd(&hs[g_m[idx]], 1);
    __syncthreads();
    for (int i = threadIdx.x; i < Vdim; i += blockDim.x)
        if (hs[i]) atomicAdd(&g_wcnt[i], hs[i]);
}

// ---------------- final scoring: hinge loss + accuracy ----------------
__global__ void final_score(const float* __restrict__ target,
                            const float* __restrict__ dis) {
    int b = blockIdx.x;
    int t = threadIdx.x;
    const float* rrow = g_r + (size_t)b * Fdim;
    const float* trow = target + (size_t)b * Fdim;
    const float* d0 = dis + (size_t)0 * Bdim * Fdim + (size_t)b * Fdim;
    const float* d1 = dis + (size_t)1 * Bdim * Fdim + (size_t)b * Fdim;
    const float* d2 = dis + (size_t)2 * Bdim * Fdim + (size_t)b * Fdim;
    float a0 = 0.f, a1 = 0.f, a2 = 0.f, a3 = 0.f;
    for (int f = t; f < Fdim; f += 256) {
        float rv = rrow[f];
        a0 += trow[f] * rv;
        a1 += d0[f] * rv;
        a2 += d1[f] * rv;
        a3 += d2[f] * rv;
    }
    __shared__ float sh[4][256];
    sh[0][t] = a0; sh[1][t] = a1; sh[2][t] = a2; sh[3][t] = a3;
    __syncthreads();
    for (int s = 128; s > 0; s >>= 1) {
        if (t < s) {
            sh[0][t] += sh[0][t + s]; sh[1][t] += sh[1][t + s];
            sh[2][t] += sh[2][t + s]; sh[3][t] += sh[3][t + s];
        }
        __syncthreads();
    }
    if (t == 0) {
        float ts = sh[0][0], s1 = sh[1][0], s2 = sh[2][0], s3 = sh[3][0];
        float loss = fmaxf(0.f, 1.f - ts + s1) + fmaxf(0.f, 1.f - ts + s2) +
                     fmaxf(0.f, 1.f - ts + s3) + 0.1f * g_vl[b];
        float es = expf(ts), e1 = expf(s1), e2 = expf(s2), e3 = expf(s3);
        float acc = (es >= e1 && es >= e2 && es >= e3) ? 1.f : 0.f;
        atomicAdd(&g_loss_sum, loss);
        atomicAdd(&g_acc_sum, acc);
    }
}

// ---------------- emit outputs: [loss, acc, m (B*31), w_counts (V)] ----------------
__global__ void emit_kernel(float* __restrict__ out, int out_size) {
    int idx = blockIdx.x * blockDim.x + threadIdx.x;
    if (idx >= out_size) return;
    const int M_OFF = 2;
    const int WC_OFF = 2 + Bdim * LP1;
    const int TOTAL = WC_OFF + Vdim;
    if (idx == 0)            out[0] = g_loss_sum / (float)Bdim;
    else if (idx == 1)       out[1] = g_acc_sum / (float)Bdim;
    else if (idx < WC_OFF)   out[idx] = (float)g_m[idx - M_OFF];
    else if (idx < TOTAL)    out[idx] = (float)g_wcnt[idx - WC_OFF];
    else                     out[idx] = 0.f;
}

// ---------------- host launcher ----------------
extern "C" void kernel_launch(void* const* d_in, const int* in_sizes, int n_in,
                              void* d_out, int out_size) {
    const float* target    = (const float*)d_in[0];
    const float* dis       = (const float*)d_in[1];
    const float* wcounts   = (const float*)d_in[2];
    const float* emb_s     = (const float*)d_in[3];
    const float* aff_s_W   = (const float*)d_in[4];
    const float* aff_s_b   = (const float*)d_in[5];
    const float* lstm_Wih  = (const float*)d_in[6];
    const float* lstm_Whh  = (const float*)d_in[7];
    const float* lstm_bih  = (const float*)d_in[8];
    const float* lstm_bhh  = (const float*)d_in[9];
    const float* lp_W      = (const float*)d_in[10];
    const float* lp_b      = (const float*)d_in[11];
    const float* emb_r     = (const float*)d_in[12];
    const float* rlstm_Wih = (const float*)d_in[13];
    const float* rlstm_Whh = (const float*)d_in[14];
    const float* rlstm_bih = (const float*)d_in[15];
    const float* rlstm_bhh = (const float*)d_in[16];
    const float* aff_r_W   = (const float*)d_in[17];
    const float* aff_r_b   = (const float*)d_in[18];

    float *Ts, *Tr, *hA, *hB, *cc, *sc, *rr;
    int *mm, *tk;
    cudaGetSymbolAddress((void**)&Ts, g_Ts);
    cudaGetSymbolAddress((void**)&Tr, g_Tr);
    cudaGetSymbolAddress((void**)&hA, g_hA);
    cudaGetSymbolAddress((void**)&hB, g_hB);
    cudaGetSymbolAddress((void**)&cc, g_c);
    cudaGetSymbolAddress((void**)&sc, g_scores);
    cudaGetSymbolAddress((void**)&rr, g_r);
    cudaGetSymbolAddress((void**)&mm, g_m);
    cudaGetSymbolAddress((void**)&tk, g_tok);

    // init
    {
        int n = Bdim * Hdim;
        init_kernel<<<(n + 255) / 256, 256>>>();
    }
    nwc_kernel<<<1, 1024>>>(wcounts);

    // precompute x-projection tables (biases folded)
    sgemm_nt<<<dim3(G4H / 64, Vdim / 64), 256>>>(emb_s, lstm_Wih, lstm_bih, lstm_bhh,
                                                 Ts, Vdim, G4H, Edim);
    sgemm_nt<<<dim3(G4H / 64, Vdim / 64), 256>>>(emb_r, rlstm_Wih, rlstm_bih, rlstm_bhh,
                                                 Tr, Vdim, G4H, Edim);

    // h0 = target @ aff_s_W^T + b
    sgemm_nt<<<dim3(Hdim / 64, Bdim / 64), 256>>>(target, aff_s_W, aff_s_b, nullptr,
                                                  hA, Bdim, Hdim, Fdim);

    // ---- sender: 30 greedy steps ----
    for (int i = 0; i < Ldim; i++) {
        float* hin  = (i & 1) ? hB : hA;
        float* hout = (i & 1) ? hA : hB;
        lstm_step<<<dim3(Hdim / 64, Bdim / 64), 256>>>(hin, cc, hout, lstm_Whh, Ts, tk, 1);
        sgemm_nt<<<dim3(Vdim / 64, Bdim / 64), 256>>>(hout, lp_W, lp_b, nullptr,
                                                      sc, Bdim, Vdim, Hdim);
        score_reduce<<<Bdim / 4, 128>>>(sc, i);
    }

    // pad + histogram
    pad_kernel<<<(Bdim * LP1 + 255) / 256, 256>>>();
    hist_kernel<<<128, 256>>>();

    // ---- receiver: 31 steps over m ----
    zero_hc_kernel<<<(Bdim * Hdim + 255) / 256, 256>>>();
    for (int t = 0; t < LP1; t++) {
        float* hin  = (t & 1) ? hB : hA;
        float* hout = (t & 1) ? hA : hB;
        lstm_step<<<dim3(Hdim / 64, Bdim / 64), 256>>>(hin, cc, hout, rlstm_Whh, Tr,
                                                       mm + t, LP1);
    }
    // final h after 31 steps is in hB (t=30 even -> out hB)
    sgemm_nt<<<dim3(Fdim / 64, Bdim / 64), 256>>>(hB, aff_r_W, aff_r_b, nullptr,
                                                  rr, Bdim, Fdim, Hdim);

    final_score<<<Bdim, 256>>>(target, dis);

    int total = 2 + Bdim * LP1 + Vdim;
    int n_emit = out_size > total ? out_size : total;
    emit_kernel<<<(n_emit + 255) / 256, 256>>>((float*)d_out, out_size);
}

// round 9
// speedup vs baseline: 1.0114x; 1.0114x over previous
#include <cuda_runtime.h>
#include <math.h>
#include <stdint.h>

#define Bdim  4096
#define Fdim  4096
#define Vdim  1024
#define Edim  512
#define Hdim  1024
#define Ldim  30
#define LP1   (Ldim + 1)
#define BOUNDT 1023
#define G4H   (4 * Hdim)

// ================= PTX helpers =================
__device__ __forceinline__ float tf32_rn(float x) {
    uint32_t u;
    asm("cvt.rna.tf32.f32 %0, %1;" : "=r"(u) : "f"(x));
    return __uint_as_float(u);
}
#define SMEM_SWIZZLE_128B(o)   ((o) ^ (((o) >> 3) & 0x70))

// Warp-level mma.sync tf32 (compiles for plain compute_103)
__device__ __forceinline__ void mma_m16n8k8(float* d, const uint32_t* a, const uint32_t* b) {
    asm volatile("mma.sync.aligned.m16n8k8.row.col.f32.tf32.tf32.f32 "
                 "{%0,%1,%2,%3}, {%4,%5,%6,%7}, {%8,%9}, {%0,%1,%2,%3};"
                 : "+f"(d[0]), "+f"(d[1]), "+f"(d[2]), "+f"(d[3])
                 : "r"(a[0]), "r"(a[1]), "r"(a[2]), "r"(a[3]), "r"(b[0]), "r"(b[1]));
}

// ================= scratch (static device globals) =================
__device__ float g_Ts[(size_t)Vdim * G4H];      // sender table, R1 layout [V][g*H + j]
__device__ float g_Tr[(size_t)Vdim * G4H];      // receiver table, gate-interleaved [V][4j+g]
__device__ float g_WrHi[(size_t)G4H * Hdim];    // receiver Whh split, gate-interleaved rows
__device__ float g_WrLo[(size_t)G4H * Hdim];
__device__ float g_hA[(size_t)Bdim * Hdim];     // sender plain h ping
__device__ float g_hB[(size_t)Bdim * Hdim];     // sender plain h pong
__device__ float g_hHiA[(size_t)Bdim * Hdim];   // receiver split h
__device__ float g_hLoA[(size_t)Bdim * Hdim];
__device__ float g_hHiB[(size_t)Bdim * Hdim];
__device__ float g_hLoB[(size_t)Bdim * Hdim];
__device__ float g_hPlain[(size_t)Bdim * Hdim]; // receiver plain h (for final r)
__device__ float g_c[(size_t)Bdim * Hdim];
__device__ float g_scores[(size_t)Bdim * Vdim]; // also temp for table precompute
__device__ float g_r[(size_t)Bdim * Fdim];
__device__ float g_nwc[Vdim];
__device__ float g_vl[Bdim];
__device__ int   g_tok[Bdim];
__device__ int   g_sl[Bdim];
__device__ int   g_m[(size_t)Bdim * LP1];
__device__ int   g_wcnt[Vdim];
__device__ float g_loss_sum;
__device__ float g_acc_sum;

__device__ __forceinline__ float sigf(float x) {
    if (x >= 0.f) return 1.f / (1.f + expf(-x));
    float e = expf(x);
    return e / (1.f + e);
}

// ================= small kernels =================
__global__ void init_kernel() {
    int idx = blockIdx.x * blockDim.x + threadIdx.x;
    if (idx < Bdim * Hdim) g_c[idx] = 0.f;
    if (idx < Bdim) {
        g_tok[idx] = BOUNDT; g_sl[idx] = LP1; g_vl[idx] = 0.f;
        g_m[(size_t)idx * LP1] = BOUNDT;
    }
    if (idx < Vdim) g_wcnt[idx] = 0;
    if (idx == 0) { g_loss_sum = 0.f; g_acc_sum = 0.f; }
}

__global__ void zero_rx_kernel() {
    int idx = blockIdx.x * blockDim.x + threadIdx.x;
    if (idx < Bdim * Hdim) { g_hHiA[idx] = 0.f; g_hLoA[idx] = 0.f; g_c[idx] = 0.f; }
}

// dst[v][4*j+g] = src[v][g*H + j]
__global__ void reorder_table(const float* __restrict__ src, float* __restrict__ dst) {
    int idx = blockIdx.x * blockDim.x + threadIdx.x;
    if (idx >= Vdim * G4H) return;
    int v = idx >> 12, r = idx & 4095;
    int j = r >> 2, g = r & 3;
    dst[idx] = src[(size_t)v * G4H + g * Hdim + j];
}

// hi/lo[(4*j+g)*H + k] = split(W[(g*H+j)*H + k])
__global__ void reorder_split_w(const float* __restrict__ src, float* __restrict__ hi,
                                float* __restrict__ lo) {
    int idx = blockIdx.x * blockDim.x + threadIdx.x;
    if (idx >= G4H * Hdim) return;
    int r = idx >> 10, k = idx & 1023;
    int j = r >> 2, g = r & 3;
    float x = src[(size_t)(g * Hdim + j) * Hdim + k];
    float h = tf32_rn(x);
    hi[idx] = h;
    lo[idx] = tf32_rn(x - h);
}

__global__ void nwc_kernel(const float* __restrict__ wc) {
    __shared__ float red[1024];
    int t = threadIdx.x;
    float v = wc[t];
    if (t == BOUNDT) v *= 0.1f;
    red[t] = v;
    __syncthreads();
    for (int s = 512; s > 0; s >>= 1) {
        if (t < s) red[t] += red[t + s];
        __syncthreads();
    }
    float denom = red[0];
    g_nwc[t] = (denom > 0.f) ? v / denom : v;
}

// ================= fp32 SGEMM (R1-exact) =================
__global__ __launch_bounds__(256)
void sgemm_nt(const float* __restrict__ A, const float* __restrict__ Bm,
              const float* __restrict__ bias1, const float* __restrict__ bias2,
              float* __restrict__ C, int M, int N, int K) {
    __shared__ __align__(16) float As[16][64];
    __shared__ __align__(16) float Bs[16][64];
    int tid = threadIdx.x;
    int tx = tid & 15, ty = tid >> 4;
    int m0 = blockIdx.y * 64, n0 = blockIdx.x * 64;
    int lrow = tid >> 2, lcol = (tid & 3) * 4;
    float acc[4][4] = {};
    for (int k0 = 0; k0 < K; k0 += 16) {
        float4 av = *(const float4*)(A + (size_t)(m0 + lrow) * K + k0 + lcol);
        float4 bv = *(const float4*)(Bm + (size_t)(n0 + lrow) * K + k0 + lcol);
        As[lcol + 0][lrow] = av.x; As[lcol + 1][lrow] = av.y;
        As[lcol + 2][lrow] = av.z; As[lcol + 3][lrow] = av.w;
        Bs[lcol + 0][lrow] = bv.x; Bs[lcol + 1][lrow] = bv.y;
        Bs[lcol + 2][lrow] = bv.z; Bs[lcol + 3][lrow] = bv.w;
        __syncthreads();
#pragma unroll
        for (int k = 0; k < 16; k++) {
            float4 a = *(const float4*)&As[k][ty << 2];
            float4 b = *(const float4*)&Bs[k][tx << 2];
            float ar[4] = {a.x, a.y, a.z, a.w};
            float br[4] = {b.x, b.y, b.z, b.w};
#pragma unroll
            for (int i = 0; i < 4; i++)
#pragma unroll
                for (int j = 0; j < 4; j++) acc[i][j] += ar[i] * br[j];
        }
        __syncthreads();
    }
    float bb[4];
#pragma unroll
    for (int j = 0; j < 4; j++) {
        int n = n0 + (tx << 2) + j;
        bb[j] = (bias1 ? bias1[n] : 0.f) + (bias2 ? bias2[n] : 0.f);
    }
#pragma unroll
    for (int i = 0; i < 4; i++) {
        float4 o = make_float4(acc[i][0] + bb[0], acc[i][1] + bb[1],
                               acc[i][2] + bb[2], acc[i][3] + bb[3]);
        *(float4*)(C + (size_t)(m0 + (ty << 2) + i) * N + n0 + (tx << 2)) = o;
    }
}

// ================= R1-exact fused fp32 LSTM step (sender) =================
__global__ __launch_bounds__(256, 2)
void lstm_step(const float* __restrict__ h_in, float* __restrict__ c_io,
               float* __restrict__ h_out,
               const float* __restrict__ Whh,  // [4H, H] original layout
               const float* __restrict__ T,    // [V, 4H] R1 layout (biases folded)
               const int* __restrict__ tok, int tok_stride) {
    __shared__ __align__(16) float As[16][64];
    __shared__ __align__(16) float Bs[4][16][64];
    int tid = threadIdx.x;
    int tx = tid & 15, ty = tid >> 4;
    int m0 = blockIdx.y * 64;   // batch rows
    int n0 = blockIdx.x * 64;   // h columns
    int lrow = tid >> 2, lcol = (tid & 3) * 4;

    float acc[4][4][4];   // [gate][i][j]
#pragma unroll
    for (int i = 0; i < 4; i++) {
        int row = m0 + (ty << 2) + i;
        int t_r = tok[(size_t)row * tok_stride];
        const float* Trow = T + (size_t)t_r * G4H + n0 + (tx << 2);
#pragma unroll
        for (int g = 0; g < 4; g++) {
            float4 v = *(const float4*)(Trow + g * Hdim);
            acc[g][i][0] = v.x; acc[g][i][1] = v.y;
            acc[g][i][2] = v.z; acc[g][i][3] = v.w;
        }
    }

    for (int k0 = 0; k0 < Hdim; k0 += 16) {
        float4 av = *(const float4*)(h_in + (size_t)(m0 + lrow) * Hdim + k0 + lcol);
        As[lcol + 0][lrow] = av.x; As[lcol + 1][lrow] = av.y;
        As[lcol + 2][lrow] = av.z; As[lcol + 3][lrow] = av.w;
#pragma unroll
        for (int g = 0; g < 4; g++) {
            float4 bv = *(const float4*)(Whh + (size_t)(g * Hdim + n0 + lrow) * Hdim + k0 + lcol);
            Bs[g][lcol + 0][lrow] = bv.x; Bs[g][lcol + 1][lrow] = bv.y;
            Bs[g][lcol + 2][lrow] = bv.z; Bs[g][lcol + 3][lrow] = bv.w;
        }
        __syncthreads();
#pragma unroll
        for (int k = 0; k < 16; k++) {
            float4 a = *(const float4*)&As[k][ty << 2];
            float ar[4] = {a.x, a.y, a.z, a.w};
#pragma unroll
            for (int g = 0; g < 4; g++) {
                float4 b = *(const float4*)&Bs[g][k][tx << 2];
                float br[4] = {b.x, b.y, b.z, b.w};
#pragma unroll
                for (int i = 0; i < 4; i++)
#pragma unroll
                    for (int j = 0; j < 4; j++) acc[g][i][j] += ar[i] * br[j];
            }
        }
        __syncthreads();
    }

#pragma unroll
    for (int i = 0; i < 4; i++) {
        int row = m0 + (ty << 2) + i;
#pragma unroll
        for (int j = 0; j < 4; j++) {
            int n = n0 + (tx << 2) + j;
            size_t off = (size_t)row * Hdim + n;
            float ig = acc[0][i][j], fg = acc[1][i][j];
            float gg = acc[2][i][j], og = acc[3][i][j];
            float c_old = c_io[off];
            float cn = sigf(fg) * c_old + sigf(ig) * tanhf(gg);
            float hn = sigf(og) * tanhf(cn);
            c_io[off] = cn;
            h_out[off] = hn;
        }
    }
}

// ================= tf32x3 tensor LSTM step (receiver only) =================
// C[128 x 128] = h @ Wre^T (rows gate-interleaved) + fused LSTM cell.
#define STAGE_BYTES 65536
#define A_HI_OFF 0
#define A_LO_OFF 16384
#define B_HI_OFF 32768
#define B_LO_OFF 49152
#define NKITER   32

__device__ __forceinline__ void lstm_cell32(int cb, const float* vals, const float* Trow,
                                            float* cRow, size_t ob,
                                            float* __restrict__ o1, float* __restrict__ o2,
                                            float* __restrict__ o3) {
#pragma unroll
    for (int t = 0; t < 8; t++) {
        int j = (cb >> 2) + t;
        float iv = vals[4 * t + 0] + Trow[cb + 4 * t + 0];
        float fv = vals[4 * t + 1] + Trow[cb + 4 * t + 1];
        float gv = vals[4 * t + 2] + Trow[cb + 4 * t + 2];
        float ov = vals[4 * t + 3] + Trow[cb + 4 * t + 3];
        float co = cRow[j];
        float cn = sigf(fv) * co + sigf(iv) * tanhf(gv);
        float hn = sigf(ov) * tanhf(cn);
        cRow[j] = cn;
        float hh = tf32_rn(hn);
        o1[ob + j] = hh;
        o2[ob + j] = tf32_rn(hn - hh);
        o3[ob + j] = hn;
    }
}

__global__ __launch_bounds__(256, 1)
void tc_lstm(const float* __restrict__ Ahi, const float* __restrict__ Alo,
             const float* __restrict__ Bhi, const float* __restrict__ Blo,
             const float* __restrict__ Taux,      // reordered table [V][4j+g]
             const int* __restrict__ tok, int tok_stride,
             float* __restrict__ c_io,
             float* __restrict__ o1, float* __restrict__ o2, float* __restrict__ o3) {
    extern __shared__ __align__(1024) char dsm[];
    const int tid = threadIdx.x;
    const int m0 = blockIdx.y * 128;
    const int nb = blockIdx.x;

    const int lane = tid & 31, grp = lane >> 2, tig = lane & 3;
    const int wid = tid >> 5;
    const int warpM = wid >> 2, warpN = wid & 3;   // 2 x 4 warps, warp tile 64x32

    float acc[4][4][4];
#pragma unroll
    for (int mi = 0; mi < 4; mi++)
#pragma unroll
        for (int ni = 0; ni < 4; ni++)
#pragma unroll
            for (int q = 0; q < 4; q++) acc[mi][ni][q] = 0.f;

    auto load_stage = [&](int kt) {
        char* sb = dsm + (kt & 1) * STAGE_BYTES;
        const int k0 = kt * 32;
#pragma unroll
        for (int t = 0; t < 4; t++) {
            int slot = tid + t * 256;
            int r = slot >> 3, c4 = slot & 7;
            uint32_t sw = SMEM_SWIZZLE_128B((uint32_t)(r * 128 + c4 * 16));
            *(float4*)(sb + A_HI_OFF + sw) =
                *((const float4*)(Ahi + (size_t)(m0 + r) * Hdim + k0) + c4);
            *(float4*)(sb + A_LO_OFF + sw) =
                *((const float4*)(Alo + (size_t)(m0 + r) * Hdim + k0) + c4);
            int grow = nb * 128 + r;
            *(float4*)(sb + B_HI_OFF + sw) =
                *((const float4*)(Bhi + (size_t)grow * Hdim + k0) + c4);
            *(float4*)(sb + B_LO_OFF + sw) =
                *((const float4*)(Blo + (size_t)grow * Hdim + k0) + c4);
        }
    };

    load_stage(0);
    __syncthreads();
    for (int kt = 0; kt < NKITER; kt++) {
        if (kt + 1 < NKITER) load_stage(kt + 1);
        const char* sb = dsm + (kt & 1) * STAGE_BYTES;
#pragma unroll
        for (int ks = 0; ks < 4; ks++) {
            uint32_t ah[4][4], al[4][4], bh[4][2], bl[4][2];
#pragma unroll
            for (int mi = 0; mi < 4; mi++) {
                int r0 = warpM * 64 + mi * 16 + grp;
                int kcol = ks * 8 + tig;
                uint32_t o00 = SMEM_SWIZZLE_128B((uint32_t)(r0 * 128 + kcol * 4));
                uint32_t o10 = SMEM_SWIZZLE_128B((uint32_t)((r0 + 8) * 128 + kcol * 4));
                uint32_t o01 = SMEM_SWIZZLE_128B((uint32_t)(r0 * 128 + (kcol + 4) * 4));
                uint32_t o11 = SMEM_SWIZZLE_128B((uint32_t)((r0 + 8) * 128 + (kcol + 4) * 4));
                ah[mi][0] = *(const uint32_t*)(sb + A_HI_OFF + o00);
                ah[mi][1] = *(const uint32_t*)(sb + A_HI_OFF + o10);
                ah[mi][2] = *(const uint32_t*)(sb + A_HI_OFF + o01);
                ah[mi][3] = *(const uint32_t*)(sb + A_HI_OFF + o11);
                al[mi][0] = *(const uint32_t*)(sb + A_LO_OFF + o00);
                al[mi][1] = *(const uint32_t*)(sb + A_LO_OFF + o10);
                al[mi][2] = *(const uint32_t*)(sb + A_LO_OFF + o01);
                al[mi][3] = *(const uint32_t*)(sb + A_LO_OFF + o11);
            }
#pragma unroll
            for (int ni = 0; ni < 4; ni++) {
                int n0 = warpN * 32 + ni * 8 + grp;
                int kcol = ks * 8 + tig;
                uint32_t o0 = SMEM_SWIZZLE_128B((uint32_t)(n0 * 128 + kcol * 4));
                uint32_t o1_ = SMEM_SWIZZLE_128B((uint32_t)(n0 * 128 + (kcol + 4) * 4));
                bh[ni][0] = *(const uint32_t*)(sb + B_HI_OFF + o0);
                bh[ni][1] = *(const uint32_t*)(sb + B_HI_OFF + o1_);
                bl[ni][0] = *(const uint32_t*)(sb + B_LO_OFF + o0);
                bl[ni][1] = *(const uint32_t*)(sb + B_LO_OFF + o1_);
            }
#pragma unroll
            for (int mi = 0; mi < 4; mi++)
#pragma unroll
                for (int ni = 0; ni < 4; ni++) mma_m16n8k8(acc[mi][ni], ah[mi], bh[ni]);
#pragma unroll
            for (int mi = 0; mi < 4; mi++)
#pragma unroll
                for (int ni = 0; ni < 4; ni++) mma_m16n8k8(acc[mi][ni], ah[mi], bl[ni]);
#pragma unroll
            for (int mi = 0; mi < 4; mi++)
#pragma unroll
                for (int ni = 0; ni < 4; ni++) mma_m16n8k8(acc[mi][ni], al[mi], bh[ni]);
        }
        __syncthreads();
    }

    // dump C frags to SMEM (overlays stage memory; all compute synced above)
    float* Csm = (float*)dsm;                      // [128][130]
#pragma unroll
    for (int mi = 0; mi < 4; mi++) {
#pragma unroll
        for (int ni = 0; ni < 4; ni++) {
            int r0 = warpM * 64 + mi * 16 + grp;
            int cc = warpN * 32 + ni * 8 + tig * 2;
            *(float2*)&Csm[(size_t)r0 * 130 + cc] = make_float2(acc[mi][ni][0], acc[mi][ni][1]);
            *(float2*)&Csm[(size_t)(r0 + 8) * 130 + cc] = make_float2(acc[mi][ni][2], acc[mi][ni][3]);
        }
    }
    __syncthreads();

    if (tid < 128) {
        const int row = m0 + tid;
        const float* crow = &Csm[(size_t)tid * 130];
        const int tv = tok[(size_t)row * tok_stride];
        const float* Trow = Taux + (size_t)tv * G4H + nb * 128;
        float* cRow = c_io + (size_t)row * Hdim + nb * 32;
        const size_t ob = (size_t)row * Hdim + nb * 32;
#pragma unroll
        for (int cb = 0; cb < 128; cb += 32) {
            float vals[32];
#pragma unroll
            for (int j = 0; j < 32; j++) vals[j] = crow[cb + j];
            lstm_cell32(cb, vals, Trow, cRow, ob, o1, o2, o3);
        }
    }
}

// ================= R1-exact argmax + CE reduce =================
__global__ void score_reduce(const float* __restrict__ scores, int step) {
    int gwarp = (blockIdx.x * blockDim.x + threadIdx.x) >> 5;
    int lane = threadIdx.x & 31;
    if (gwarp >= Bdim) return;
    const float* srow = scores + (size_t)gwarp * Vdim;

    float lvals[32];
    float best = -INFINITY; int bidx = 0;
    float lmax = -INFINITY;
#pragma unroll
    for (int j = 0; j < 32; j++) {
        int idx = lane + j * 32;
        float s = srow[idx];
        float l = s - g_nwc[idx];
        lvals[j] = l;
        if (s > best) { best = s; bidx = idx; }
        lmax = fmaxf(lmax, l);
    }
#pragma unroll
    for (int off = 16; off; off >>= 1) {
        float ov = __shfl_down_sync(0xffffffffu, best, off);
        int   oi = __shfl_down_sync(0xffffffffu, bidx, off);
        if (ov > best || (ov == best && oi < bidx)) { best = ov; bidx = oi; }
        lmax = fmaxf(lmax, __shfl_down_sync(0xffffffffu, lmax, off));
    }
    bidx = __shfl_sync(0xffffffffu, bidx, 0);
    lmax = __shfl_sync(0xffffffffu, lmax, 0);

    float se = 0.f;
#pragma unroll
    for (int j = 0; j < 32; j++) se += expf(lvals[j] - lmax);
#pragma unroll
    for (int off = 16; off; off >>= 1) se += __shfl_down_sync(0xffffffffu, se, off);

    if (lane == 0) {
        float l_tok = srow[bidx] - g_nwc[bidx];
        float ce = logf(se) + lmax - l_tok;
        g_m[(size_t)gwarp * LP1 + step + 1] = bidx;
        g_tok[gwarp] = bidx;
        if (bidx == BOUNDT && g_sl[gwarp] == LP1) g_sl[gwarp] = step + 2;
        g_vl[gwarp] += ce;
    }
}

__global__ void pad_kernel() {
    int idx = blockIdx.x * blockDim.x + threadIdx.x;
    if (idx >= Bdim * LP1) return;
    int b = idx / LP1, p = idx % LP1;
    if (p >= g_sl[b]) g_m[idx] = BOUNDT;
}

__global__ void hist_kernel() {
    __shared__ int hs[Vdim];
    for (int i = threadIdx.x; i < Vdim; i += blockDim.x) hs[i] = 0;
    __syncthreads();
    int total = Bdim * LP1;
    for (int idx = blockIdx.x * blockDim.x + threadIdx.x; idx < total;
         idx += gridDim.x * blockDim.x)
        atomicAdd(&hs[g_m[idx]], 1);
    __syncthreads();
    for (int i = threadIdx.x; i < Vdim; i += blockDim.x)
        if (hs[i]) atomicAdd(&g_wcnt[i], hs[i]);
}

__global__ void final_score(const float* __restrict__ target,
                            const float* __restrict__ dis) {
    int b = blockIdx.x;
    int t = threadIdx.x;
    const float* rrow = g_r + (size_t)b * Fdim;
    const float* trow = target + (size_t)b * Fdim;
    const float* d0 = dis + (size_t)b * Fdim;
    const float* d1 = dis + (size_t)Bdim * Fdim + (size_t)b * Fdim;
    const float* d2 = dis + (size_t)2 * Bdim * Fdim + (size_t)b * Fdim;
    float a0 = 0.f, a1 = 0.f, a2 = 0.f, a3 = 0.f;
    for (int f = t; f < Fdim; f += 256) {
        float rv = rrow[f];
        a0 += trow[f] * rv; a1 += d0[f] * rv; a2 += d1[f] * rv; a3 += d2[f] * rv;
    }
    __shared__ float sh[4][256];
    sh[0][t] = a0; sh[1][t] = a1; sh[2][t] = a2; sh[3][t] = a3;
    __syncthreads();
    for (int s = 128; s > 0; s >>= 1) {
        if (t < s) {
            sh[0][t] += sh[0][t + s]; sh[1][t] += sh[1][t + s];
            sh[2][t] += sh[2][t + s]; sh[3][t] += sh[3][t + s];
        }
        __syncthreads();
    }
    if (t == 0) {
        float ts = sh[0][0], s1 = sh[1][0], s2 = sh[2][0], s3 = sh[3][0];
        float loss = fmaxf(0.f, 1.f - ts + s1) + fmaxf(0.f, 1.f - ts + s2) +
                     fmaxf(0.f, 1.f - ts + s3) + 0.1f * g_vl[b];
        float es = expf(ts), e1 = expf(s1), e2 = expf(s2), e3 = expf(s3);
        float acc = (es >= e1 && es >= e2 && es >= e3) ? 1.f : 0.f;
        atomicAdd(&g_loss_sum, loss);
        atomicAdd(&g_acc_sum, acc);
    }
}

__global__ void emit_kernel(float* __restrict__ out, int out_size) {
    int idx = blockIdx.x * blockDim.x + threadIdx.x;
    if (idx >= out_size) return;
    const int M_OFF = 2;
    const int WC_OFF = 2 + Bdim * LP1;
    const int TOTAL = WC_OFF + Vdim;
    if (idx == 0)            out[0] = g_loss_sum / (float)Bdim;
    else if (idx == 1)       out[1] = g_acc_sum / (float)Bdim;
    else if (idx < WC_OFF)   out[idx] = (float)g_m[idx - M_OFF];
    else if (idx < TOTAL)    out[idx] = (float)g_wcnt[idx - WC_OFF];
    else                     out[idx] = 0.f;
}

// ================= host launcher =================
extern "C" void kernel_launch(void* const* d_in, const int* in_sizes, int n_in,
                              void* d_out, int out_size) {
    const float* target    = (const float*)d_in[0];
    const float* dis       = (const float*)d_in[1];
    const float* wcounts   = (const float*)d_in[2];
    const float* emb_s     = (const float*)d_in[3];
    const float* aff_s_W   = (const float*)d_in[4];
    const float* aff_s_b   = (const float*)d_in[5];
    const float* lstm_Wih  = (const float*)d_in[6];
    const float* lstm_Whh  = (const float*)d_in[7];
    const float* lstm_bih  = (const float*)d_in[8];
    const float* lstm_bhh  = (const float*)d_in[9];
    const float* lp_W      = (const float*)d_in[10];
    const float* lp_b      = (const float*)d_in[11];
    const float* emb_r     = (const float*)d_in[12];
    const float* rlstm_Wih = (const float*)d_in[13];
    const float* rlstm_Whh = (const float*)d_in[14];
    const float* rlstm_bih = (const float*)d_in[15];
    const float* rlstm_bhh = (const float*)d_in[16];
    const float* aff_r_W   = (const float*)d_in[17];
    const float* aff_r_b   = (const float*)d_in[18];

    float *Ts, *Tr, *WrHi, *WrLo;
    float *hA, *hB, *hHiA, *hLoA, *hHiB, *hLoB, *hPlain, *cc, *sc, *rr;
    int *mm, *tk;
    cudaGetSymbolAddress((void**)&Ts, g_Ts);
    cudaGetSymbolAddress((void**)&Tr, g_Tr);
    cudaGetSymbolAddress((void**)&WrHi, g_WrHi);
    cudaGetSymbolAddress((void**)&WrLo, g_WrLo);
    cudaGetSymbolAddress((void**)&hA, g_hA);
    cudaGetSymbolAddress((void**)&hB, g_hB);
    cudaGetSymbolAddress((void**)&hHiA, g_hHiA);
    cudaGetSymbolAddress((void**)&hLoA, g_hLoA);
    cudaGetSymbolAddress((void**)&hHiB, g_hHiB);
    cudaGetSymbolAddress((void**)&hLoB, g_hLoB);
    cudaGetSymbolAddress((void**)&hPlain, g_hPlain);
    cudaGetSymbolAddress((void**)&cc, g_c);
    cudaGetSymbolAddress((void**)&sc, g_scores);
    cudaGetSymbolAddress((void**)&rr, g_r);
    cudaGetSymbolAddress((void**)&mm, g_m);
    cudaGetSymbolAddress((void**)&tk, g_tok);

    cudaFuncSetAttribute(tc_lstm, cudaFuncAttributeMaxDynamicSharedMemorySize, 2 * STAGE_BYTES);

    init_kernel<<<(Bdim * Hdim + 255) / 256, 256>>>();
    nwc_kernel<<<1, 1024>>>(wcounts);

    // sender table (R1 layout, biases folded)
    sgemm_nt<<<dim3(G4H / 64, Vdim / 64), 256>>>(emb_s, lstm_Wih, lstm_bih, lstm_bhh,
                                                 Ts, Vdim, G4H, Edim);
    // receiver table -> temp -> gate-interleaved reorder
    sgemm_nt<<<dim3(G4H / 64, Vdim / 64), 256>>>(emb_r, rlstm_Wih, rlstm_bih, rlstm_bhh,
                                                 sc, Vdim, G4H, Edim);
    reorder_table<<<(Vdim * G4H + 255) / 256, 256>>>(sc, Tr);
    // receiver weight split (gate-interleaved rows)
    reorder_split_w<<<(G4H * Hdim + 255) / 256, 256>>>(rlstm_Whh, WrHi, WrLo);

    // h0 = target @ aff_s_W^T + b  (fp32, R1-exact)
    sgemm_nt<<<dim3(Hdim / 64, Bdim / 64), 256>>>(target, aff_s_W, aff_s_b, nullptr,
                                                  hA, Bdim, Hdim, Fdim);

    // ---- sender: 30 greedy steps, fully fp32 (R1-exact arithmetic) ----
    for (int i = 0; i < Ldim; i++) {
        float* hin  = (i & 1) ? hB : hA;
        float* hout = (i & 1) ? hA : hB;
        lstm_step<<<dim3(Hdim / 64, Bdim / 64), 256>>>(hin, cc, hout, lstm_Whh, Ts, tk, 1);
        sgemm_nt<<<dim3(Vdim / 64, Bdim / 64), 256>>>(hout, lp_W, lp_b, nullptr,
                                                      sc, Bdim, Vdim, Hdim);
        score_reduce<<<Bdim / 4, 128>>>(sc, i);
    }

    pad_kernel<<<(Bdim * LP1 + 255) / 256, 256>>>();
    hist_kernel<<<128, 256>>>();

    // ---- receiver: 31 steps, tf32x3 tensor cores (no decisions downstream) ----
    zero_rx_kernel<<<(Bdim * Hdim + 255) / 256, 256>>>();
    const dim3 gridR(32, 32);   // 32 hcol-blocks x 32 row-blocks
    for (int t = 0; t < LP1; t++) {
        float* hiI = (t & 1) ? hHiB : hHiA;  float* loI = (t & 1) ? hLoB : hLoA;
        float* hiO = (t & 1) ? hHiA : hHiB;  float* loO = (t & 1) ? hLoA : hLoB;
        tc_lstm<<<gridR, 256, 2 * STAGE_BYTES>>>(hiI, loI, WrHi, WrLo, Tr, mm + t, LP1,
                                                 cc, hiO, loO, hPlain);
    }

    // r = h_final @ aff_r_W^T + b  (h_final in hPlain)
    sgemm_nt<<<dim3(Fdim / 64, Bdim / 64), 256>>>(hPlain, aff_r_W, aff_r_b, nullptr,
                                                  rr, Bdim, Fdim, Hdim);

    final_score<<<Bdim, 256>>>(target, dis);

    int total = 2 + Bdim * LP1 + Vdim;
    int n_emit = out_size > total ? out_size : total;
    emit_kernel<<<(n_emit + 255) / 256, 256>>>((float*)d_out, out_size);
}

// round 10
// speedup vs baseline: 1.0331x; 1.0215x over previous
#include <cuda_runtime.h>
#include <math.h>
#include <stdint.h>

#define Bdim  4096
#define Fdim  4096
#define Vdim  1024
#define Edim  512
#define Hdim  1024
#define Ldim  30
#define LP1   (Ldim + 1)
#define BOUNDT 1023
#define G4H   (4 * Hdim)

// ================= scratch (static device globals) =================
__device__ float g_Ts[(size_t)Vdim * G4H];      // sender table [V][g*H + j] (biases folded)
__device__ float g_Tr[(size_t)Vdim * G4H];      // receiver table, same layout
__device__ float g_hA[(size_t)Bdim * Hdim];
__device__ float g_hB[(size_t)Bdim * Hdim];
__device__ float g_c [(size_t)Bdim * Hdim];
__device__ float g_scores[(size_t)Bdim * Vdim];
__device__ float g_r[(size_t)Bdim * Fdim];
__device__ float g_nwc[Vdim];
__device__ float g_vl[Bdim];
__device__ int   g_tok[Bdim];
__device__ int   g_sl[Bdim];
__device__ int   g_m[(size_t)Bdim * LP1];
__device__ int   g_wcnt[Vdim];
__device__ float g_loss_sum;
__device__ float g_acc_sum;

__device__ __forceinline__ float sigf(float x) {
    if (x >= 0.f) return 1.f / (1.f + expf(-x));
    float e = expf(x);
    return e / (1.f + e);
}

// ================= small kernels =================
__global__ void init_kernel() {
    int idx = blockIdx.x * blockDim.x + threadIdx.x;
    if (idx < Bdim * Hdim) g_c[idx] = 0.f;
    if (idx < Bdim) {
        g_tok[idx] = BOUNDT; g_sl[idx] = LP1; g_vl[idx] = 0.f;
        g_m[(size_t)idx * LP1] = BOUNDT;
    }
    if (idx < Vdim) g_wcnt[idx] = 0;
    if (idx == 0) { g_loss_sum = 0.f; g_acc_sum = 0.f; }
}

__global__ void zero_hc_kernel() {
    int idx = blockIdx.x * blockDim.x + threadIdx.x;
    if (idx < Bdim * Hdim) { g_hA[idx] = 0.f; g_c[idx] = 0.f; }
}

__global__ void nwc_kernel(const float* __restrict__ wc) {
    __shared__ float red[1024];
    int t = threadIdx.x;
    float v = wc[t];
    if (t == BOUNDT) v *= 0.1f;
    red[t] = v;
    __syncthreads();
    for (int s = 512; s > 0; s >>= 1) {
        if (t < s) red[t] += red[t + s];
        __syncthreads();
    }
    float denom = red[0];
    g_nwc[t] = (denom > 0.f) ? v / denom : v;
}

// ================= fp32 SGEMM (R1-exact; DO NOT CHANGE ARITHMETIC) =================
__global__ __launch_bounds__(256)
void sgemm_nt(const float* __restrict__ A, const float* __restrict__ Bm,
              const float* __restrict__ bias1, const float* __restrict__ bias2,
              float* __restrict__ C, int M, int N, int K) {
    __shared__ __align__(16) float As[16][64];
    __shared__ __align__(16) float Bs[16][64];
    int tid = threadIdx.x;
    int tx = tid & 15, ty = tid >> 4;
    int m0 = blockIdx.y * 64, n0 = blockIdx.x * 64;
    int lrow = tid >> 2, lcol = (tid & 3) * 4;
    float acc[4][4] = {};
    for (int k0 = 0; k0 < K; k0 += 16) {
        float4 av = *(const float4*)(A + (size_t)(m0 + lrow) * K + k0 + lcol);
        float4 bv = *(const float4*)(Bm + (size_t)(n0 + lrow) * K + k0 + lcol);
        As[lcol + 0][lrow] = av.x; As[lcol + 1][lrow] = av.y;
        As[lcol + 2][lrow] = av.z; As[lcol + 3][lrow] = av.w;
        Bs[lcol + 0][lrow] = bv.x; Bs[lcol + 1][lrow] = bv.y;
        Bs[lcol + 2][lrow] = bv.z; Bs[lcol + 3][lrow] = bv.w;
        __syncthreads();
#pragma unroll
        for (int k = 0; k < 16; k++) {
            float4 a = *(const float4*)&As[k][ty << 2];
            float4 b = *(const float4*)&Bs[k][tx << 2];
            float ar[4] = {a.x, a.y, a.z, a.w};
            float br[4] = {b.x, b.y, b.z, b.w};
#pragma unroll
            for (int i = 0; i < 4; i++)
#pragma unroll
                for (int j = 0; j < 4; j++) acc[i][j] += ar[i] * br[j];
        }
        __syncthreads();
    }
    float bb[4];
#pragma unroll
    for (int j = 0; j < 4; j++) {
        int n = n0 + (tx << 2) + j;
        bb[j] = (bias1 ? bias1[n] : 0.f) + (bias2 ? bias2[n] : 0.f);
    }
#pragma unroll
    for (int i = 0; i < 4; i++) {
        float4 o = make_float4(acc[i][0] + bb[0], acc[i][1] + bb[1],
                               acc[i][2] + bb[2], acc[i][3] + bb[3]);
        *(float4*)(C + (size_t)(m0 + (ty << 2) + i) * N + n0 + (tx << 2)) = o;
    }
}

// ================= fused fp32 LSTM step — double-buffered =================
// Per-element arithmetic IDENTICAL to R1: acc seeded from T[tok], then
// FFMA over k = 0..1023 in ascending order. Only the load/sync schedule changed.
__global__ __launch_bounds__(256, 2)
void lstm_step(const float* __restrict__ h_in, float* __restrict__ c_io,
               float* __restrict__ h_out,
               const float* __restrict__ Whh,  // [4H, H]
               const float* __restrict__ T,    // [V, 4H] (biases folded)
               const int* __restrict__ tok, int tok_stride) {
    __shared__ __align__(16) float As[2][16][64];
    __shared__ __align__(16) float Bs[2][4][16][64];
    int tid = threadIdx.x;
    int tx = tid & 15, ty = tid >> 4;
    int m0 = blockIdx.y * 64;   // batch rows
    int n0 = blockIdx.x * 64;   // h columns
    int lrow = tid >> 2, lcol = (tid & 3) * 4;

    float acc[4][4][4];   // [gate][i][j]
    // seed with gathered table rows (identical to R1)
#pragma unroll
    for (int i = 0; i < 4; i++) {
        int row = m0 + (ty << 2) + i;
        int t_r = tok[(size_t)row * tok_stride];
        const float* Trow = T + (size_t)t_r * G4H + n0 + (tx << 2);
#pragma unroll
        for (int g = 0; g < 4; g++) {
            float4 v = *(const float4*)(Trow + g * Hdim);
            acc[g][i][0] = v.x; acc[g][i][1] = v.y;
            acc[g][i][2] = v.z; acc[g][i][3] = v.w;
        }
    }

    const float* pa = h_in + (size_t)(m0 + lrow) * Hdim + lcol;
    const float* pb0 = Whh + (size_t)(0 * Hdim + n0 + lrow) * Hdim + lcol;
    const float* pb1 = Whh + (size_t)(1 * Hdim + n0 + lrow) * Hdim + lcol;
    const float* pb2 = Whh + (size_t)(2 * Hdim + n0 + lrow) * Hdim + lcol;
    const float* pb3 = Whh + (size_t)(3 * Hdim + n0 + lrow) * Hdim + lcol;

    // preload k-tile 0 into buffer 0
    {
        float4 av = *(const float4*)(pa);
        float4 b0 = *(const float4*)(pb0);
        float4 b1 = *(const float4*)(pb1);
        float4 b2 = *(const float4*)(pb2);
        float4 b3 = *(const float4*)(pb3);
        As[0][lcol + 0][lrow] = av.x; As[0][lcol + 1][lrow] = av.y;
        As[0][lcol + 2][lrow] = av.z; As[0][lcol + 3][lrow] = av.w;
        Bs[0][0][lcol + 0][lrow] = b0.x; Bs[0][0][lcol + 1][lrow] = b0.y;
        Bs[0][0][lcol + 2][lrow] = b0.z; Bs[0][0][lcol + 3][lrow] = b0.w;
        Bs[0][1][lcol + 0][lrow] = b1.x; Bs[0][1][lcol + 1][lrow] = b1.y;
        Bs[0][1][lcol + 2][lrow] = b1.z; Bs[0][1][lcol + 3][lrow] = b1.w;
        Bs[0][2][lcol + 0][lrow] = b2.x; Bs[0][2][lcol + 1][lrow] = b2.y;
        Bs[0][2][lcol + 2][lrow] = b2.z; Bs[0][2][lcol + 3][lrow] = b2.w;
        Bs[0][3][lcol + 0][lrow] = b3.x; Bs[0][3][lcol + 1][lrow] = b3.y;
        Bs[0][3][lcol + 2][lrow] = b3.z; Bs[0][3][lcol + 3][lrow] = b3.w;
    }
    __syncthreads();

    const int NT = Hdim / 16;   // 64 k-tiles
    for (int kt = 0; kt < NT; kt++) {
        const int buf = kt & 1;
        // prefetch next tile from GMEM (latency hidden under compute below)
        float4 pav, pb0v, pb1v, pb2v, pb3v;
        if (kt + 1 < NT) {
            int nk = (kt + 1) * 16;
            pav  = *(const float4*)(pa  + nk);
            pb0v = *(const float4*)(pb0 + nk);
            pb1v = *(const float4*)(pb1 + nk);
            pb2v = *(const float4*)(pb2 + nk);
            pb3v = *(const float4*)(pb3 + nk);
        }
        // compute tile kt (inner chain identical to R1)
#pragma unroll
        for (int k = 0; k < 16; k++) {
            float4 a = *(const float4*)&As[buf][k][ty << 2];
            float ar[4] = {a.x, a.y, a.z, a.w};
#pragma unroll
            for (int g = 0; g < 4; g++) {
                float4 b = *(const float4*)&Bs[buf][g][k][tx << 2];
                float br[4] = {b.x, b.y, b.z, b.w};
#pragma unroll
                for (int i = 0; i < 4; i++)
#pragma unroll
                    for (int j = 0; j < 4; j++) acc[g][i][j] += ar[i] * br[j];
            }
        }
        // stage prefetched tile into alternate buffer
        if (kt + 1 < NT) {
            const int nb = buf ^ 1;
            As[nb][lcol + 0][lrow] = pav.x; As[nb][lcol + 1][lrow] = pav.y;
            As[nb][lcol + 2][lrow] = pav.z; As[nb][lcol + 3][lrow] = pav.w;
            Bs[nb][0][lcol + 0][lrow] = pb0v.x; Bs[nb][0][lcol + 1][lrow] = pb0v.y;
            Bs[nb][0][lcol + 2][lrow] = pb0v.z; Bs[nb][0][lcol + 3][lrow] = pb0v.w;
            Bs[nb][1][lcol + 0][lrow] = pb1v.x; Bs[nb][1][lcol + 1][lrow] = pb1v.y;
            Bs[nb][1][lcol + 2][lrow] = pb1v.z; Bs[nb][1][lcol + 3][lrow] = pb1v.w;
            Bs[nb][2][lcol + 0][lrow] = pb2v.x; Bs[nb][2][lcol + 1][lrow] = pb2v.y;
            Bs[nb][2][lcol + 2][lrow] = pb2v.z; Bs[nb][2][lcol + 3][lrow] = pb2v.w;
            Bs[nb][3][lcol + 0][lrow] = pb3v.x; Bs[nb][3][lcol + 1][lrow] = pb3v.y;
            Bs[nb][3][lcol + 2][lrow] = pb3v.z; Bs[nb][3][lcol + 3][lrow] = pb3v.w;
        }
        __syncthreads();
    }

    // LSTM cell epilogue (identical to R1; gate order i,f,g,o)
#pragma unroll
    for (int i = 0; i < 4; i++) {
        int row = m0 + (ty << 2) + i;
#pragma unroll
        for (int j = 0; j < 4; j++) {
            int n = n0 + (tx << 2) + j;
            size_t off = (size_t)row * Hdim + n;
            float ig = acc[0][i][j], fg = acc[1][i][j];
            float gg = acc[2][i][j], og = acc[3][i][j];
            float c_old = c_io[off];
            float cn = sigf(fg) * c_old + sigf(ig) * tanhf(gg);
            float hn = sigf(og) * tanhf(cn);
            c_io[off] = cn;
            h_out[off] = hn;
        }
    }
}

// ================= R1-exact argmax + CE reduce =================
__global__ void score_reduce(const float* __restrict__ scores, int step) {
    int gwarp = (blockIdx.x * blockDim.x + threadIdx.x) >> 5;
    int lane = threadIdx.x & 31;
    if (gwarp >= Bdim) return;
    const float* srow = scores + (size_t)gwarp * Vdim;

    float lvals[32];
    float best = -INFINITY; int bidx = 0;
    float lmax = -INFINITY;
#pragma unroll
    for (int j = 0; j < 32; j++) {
        int idx = lane + j * 32;
        float s = srow[idx];
        float l = s - g_nwc[idx];
        lvals[j] = l;
        if (s > best) { best = s; bidx = idx; }
        lmax = fmaxf(lmax, l);
    }
#pragma unroll
    for (int off = 16; off; off >>= 1) {
        float ov = __shfl_down_sync(0xffffffffu, best, off);
        int   oi = __shfl_down_sync(0xffffffffu, bidx, off);
        if (ov > best || (ov == best && oi < bidx)) { best = ov; bidx = oi; }
        lmax = fmaxf(lmax, __shfl_down_sync(0xffffffffu, lmax, off));
    }
    bidx = __shfl_sync(0xffffffffu, bidx, 0);
    lmax = __shfl_sync(0xffffffffu, lmax, 0);

    float se = 0.f;
#pragma unroll
    for (int j = 0; j < 32; j++) se += expf(lvals[j] - lmax);
#pragma unroll
    for (int off = 16; off; off >>= 1) se += __shfl_down_sync(0xffffffffu, se, off);

    if (lane == 0) {
        float l_tok = srow[bidx] - g_nwc[bidx];
        float ce = logf(se) + lmax - l_tok;
        g_m[(size_t)gwarp * LP1 + step + 1] = bidx;
        g_tok[gwarp] = bidx;
        if (bidx == BOUNDT && g_sl[gwarp] == LP1) g_sl[gwarp] = step + 2;
        g_vl[gwarp] += ce;
    }
}

__global__ void pad_kernel() {
    int idx = blockIdx.x * blockDim.x + threadIdx.x;
    if (idx >= Bdim * LP1) return;
    int b = idx / LP1, p = idx % LP1;
    if (p >= g_sl[b]) g_m[idx] = BOUNDT;
}

__global__ void hist_kernel() {
    __shared__ int hs[Vdim];
    for (int i = threadIdx.x; i < Vdim; i += blockDim.x) hs[i] = 0;
    __syncthreads();
    int total = Bdim * LP1;
    for (int idx = blockIdx.x * blockDim.x + threadIdx.x; idx < total;
         idx += gridDim.x * blockDim.x)
        atomicAdd(&hs[g_m[idx]], 1);
    __syncthreads();
    for (int i = threadIdx.x; i < Vdim; i += blockDim.x)
        if (hs[i]) atomicAdd(&g_wcnt[i], hs[i]);
}

__global__ void final_score(const float* __restrict__ target,
                            const float* __restrict__ dis) {
    int b = blockIdx.x;
    int t = threadIdx.x;
    const float* rrow = g_r + (size_t)b * Fdim;
    const float* trow = target + (size_t)b * Fdim;
    const float* d0 = dis + (size_t)b * Fdim;
    const float* d1 = dis + (size_t)Bdim * Fdim + (size_t)b * Fdim;
    const float* d2 = dis + (size_t)2 * Bdim * Fdim + (size_t)b * Fdim;
    float a0 = 0.f, a1 = 0.f, a2 = 0.f, a3 = 0.f;
    for (int f = t; f < Fdim; f += 256) {
        float rv = rrow[f];
        a0 += trow[f] * rv; a1 += d0[f] * rv; a2 += d1[f] * rv; a3 += d2[f] * rv;
    }
    __shared__ float sh[4][256];
    sh[0][t] = a0; sh[1][t] = a1; sh[2][t] = a2; sh[3][t] = a3;
    __syncthreads();
    for (int s = 128; s > 0; s >>= 1) {
        if (t < s) {
            sh[0][t] += sh[0][t + s]; sh[1][t] += sh[1][t + s];
            sh[2][t] += sh[2][t + s]; sh[3][t] += sh[3][t + s];
        }
        __syncthreads();
    }
    if (t == 0) {
        float ts = sh[0][0], s1 = sh[1][0], s2 = sh[2][0], s3 = sh[3][0];
        float loss = fmaxf(0.f, 1.f - ts + s1) + fmaxf(0.f, 1.f - ts + s2) +
                     fmaxf(0.f, 1.f - ts + s3) + 0.1f * g_vl[b];
        float es = expf(ts), e1 = expf(s1), e2 = expf(s2), e3 = expf(s3);
        float acc = (es >= e1 && es >= e2 && es >= e3) ? 1.f : 0.f;
        atomicAdd(&g_loss_sum, loss);
        atomicAdd(&g_acc_sum, acc);
    }
}

__global__ void emit_kernel(float* __restrict__ out, int out_size) {
    int idx = blockIdx.x * blockDim.x + threadIdx.x;
    if (idx >= out_size) return;
    const int M_OFF = 2;
    const int WC_OFF = 2 + Bdim * LP1;
    const int TOTAL = WC_OFF + Vdim;
    if (idx == 0)            out[0] = g_loss_sum / (float)Bdim;
    else if (idx == 1)       out[1] = g_acc_sum / (float)Bdim;
    else if (idx < WC_OFF)   out[idx] = (float)g_m[idx - M_OFF];
    else if (idx < TOTAL)    out[idx] = (float)g_wcnt[idx - WC_OFF];
    else                     out[idx] = 0.f;
}

// ================= host launcher =================
extern "C" void kernel_launch(void* const* d_in, const int* in_sizes, int n_in,
                              void* d_out, int out_size) {
    const float* target    = (const float*)d_in[0];
    const float* dis       = (const float*)d_in[1];
    const float* wcounts   = (const float*)d_in[2];
    const float* emb_s     = (const float*)d_in[3];
    const float* aff_s_W   = (const float*)d_in[4];
    const float* aff_s_b   = (const float*)d_in[5];
    const float* lstm_Wih  = (const float*)d_in[6];
    const float* lstm_Whh  = (const float*)d_in[7];
    const float* lstm_bih  = (const float*)d_in[8];
    const float* lstm_bhh  = (const float*)d_in[9];
    const float* lp_W      = (const float*)d_in[10];
    const float* lp_b      = (const float*)d_in[11];
    const float* emb_r     = (const float*)d_in[12];
    const float* rlstm_Wih = (const float*)d_in[13];
    const float* rlstm_Whh = (const float*)d_in[14];
    const float* rlstm_bih = (const float*)d_in[15];
    const float* rlstm_bhh = (const float*)d_in[16];
    const float* aff_r_W   = (const float*)d_in[17];
    const float* aff_r_b   = (const float*)d_in[18];

    float *Ts, *Tr, *hA, *hB, *cc, *sc, *rr;
    int *mm, *tk;
    cudaGetSymbolAddress((void**)&Ts, g_Ts);
    cudaGetSymbolAddress((void**)&Tr, g_Tr);
    cudaGetSymbolAddress((void**)&hA, g_hA);
    cudaGetSymbolAddress((void**)&hB, g_hB);
    cudaGetSymbolAddress((void**)&cc, g_c);
    cudaGetSymbolAddress((void**)&sc, g_scores);
    cudaGetSymbolAddress((void**)&rr, g_r);
    cudaGetSymbolAddress((void**)&mm, g_m);
    cudaGetSymbolAddress((void**)&tk, g_tok);

    init_kernel<<<(Bdim * Hdim + 255) / 256, 256>>>();
    nwc_kernel<<<1, 1024>>>(wcounts);

    // x-projection tables (biases folded), fp32 — R1 layout, no reorder
    sgemm_nt<<<dim3(G4H / 64, Vdim / 64), 256>>>(emb_s, lstm_Wih, lstm_bih, lstm_bhh,
                                                 Ts, Vdim, G4H, Edim);
    sgemm_nt<<<dim3(G4H / 64, Vdim / 64), 256>>>(emb_r, rlstm_Wih, rlstm_bih, rlstm_bhh,
                                                 Tr, Vdim, G4H, Edim);

    // h0 = target @ aff_s_W^T + b
    sgemm_nt<<<dim3(Hdim / 64, Bdim / 64), 256>>>(target, aff_s_W, aff_s_b, nullptr,
                                                  hA, Bdim, Hdim, Fdim);

    // ---- sender: 30 greedy steps (all fp32, bit-identical decisions) ----
    for (int i = 0; i < Ldim; i++) {
        float* hin  = (i & 1) ? hB : hA;
        float* hout = (i & 1) ? hA : hB;
        lstm_step<<<dim3(Hdim / 64, Bdim / 64), 256>>>(hin, cc, hout, lstm_Whh, Ts, tk, 1);
        sgemm_nt<<<dim3(Vdim / 64, Bdim / 64), 256>>>(hout, lp_W, lp_b, nullptr,
                                                      sc, Bdim, Vdim, Hdim);
        score_reduce<<<Bdim / 4, 128>>>(sc, i);
    }

    pad_kernel<<<(Bdim * LP1 + 255) / 256, 256>>>();
    hist_kernel<<<128, 256>>>();

    // ---- receiver: 31 steps on the same fast fp32 kernel ----
    zero_hc_kernel<<<(Bdim * Hdim + 255) / 256, 256>>>();
    for (int t = 0; t < LP1; t++) {
        float* hin  = (t & 1) ? hB : hA;
        float* hout = (t & 1) ? hA : hB;
        lstm_step<<<dim3(Hdim / 64, Bdim / 64), 256>>>(hin, cc, hout, rlstm_Whh, Tr,
                                                       mm + t, LP1);
    }

    // r = h_final @ aff_r_W^T + b  (t=30 even -> final h in hB)
    sgemm_nt<<<dim3(Fdim / 64, Bdim / 64), 256>>>(hB, aff_r_W, aff_r_b, nullptr,
                                                  rr, Bdim, Fdim, Hdim);

    final_score<<<Bdim, 256>>>(target, dis);

    int total = 2 + Bdim * LP1 + Vdim;
    int n_emit = out_size > total ? out_size : total;
    emit_kernel<<<(n_emit + 255) / 256, 256>>>((float*)d_out, out_size);
}